// round 6
// baseline (speedup 1.0000x reference)
#include <cuda_runtime.h>
#include <cuda_fp16.h>
#include <math.h>
#include <stdint.h>

#define Bv  4
#define Tv  2048
#define Cv  2048
#define Hv  16
#define HDv 128
#define BHv (Bv*Hv)

// ---------------- scratch (device globals; no allocation allowed) ----------------
__device__ float  g_q [(size_t)BHv * Tv * HDv];    // fp32 Q before rope
__device__ float  g_k [(size_t)BHv * Tv * HDv];    // fp32 K before rope
__device__ __half g_qh[(size_t)BHv * Tv * HDv];    // fp16 Q after rope (scale folded)
__device__ __half g_kh[(size_t)BHv * Tv * HDv];
__device__ __half g_vh[(size_t)BHv * Tv * HDv];
__device__ __half g_yh[(size_t)Bv * Tv * Cv];      // attention out
__device__ __half g_xh[(size_t)Bv * Tv * Cv];      // x in fp16
__device__ __half g_wh[(size_t)4 * Cv * Cv];       // wq,wk,wv,wo in fp16

__device__ __forceinline__ unsigned h2pack(float a, float b) {
    __half2 h = __floats2half2_rn(a, b);
    return *(unsigned*)&h;
}

__device__ __forceinline__ void mma16816(float* c, const uint4& a, const uint2& b) {
    asm volatile(
        "mma.sync.aligned.m16n8k16.row.col.f32.f16.f16.f32 "
        "{%0,%1,%2,%3}, {%4,%5,%6,%7}, {%8,%9}, {%0,%1,%2,%3};\n"
        : "+f"(c[0]), "+f"(c[1]), "+f"(c[2]), "+f"(c[3])
        : "r"(a.x), "r"(a.y), "r"(a.z), "r"(a.w), "r"(b.x), "r"(b.y));
}

// ---------------- pre-convert fp32 -> fp16 ----------------
// dst_sel: 0 -> g_xh, 1 -> g_wh (+dstoff)
__global__ void cvt_kernel(const float* __restrict__ src, int dst_sel, size_t dstoff)
{
    size_t f = ((size_t)blockIdx.x * blockDim.x + threadIdx.x) * 4;
    float4 v = *(const float4*)(src + f);
    __half* dst = (dst_sel == 0) ? g_xh : (g_wh + dstoff);
    uint2 u = make_uint2(h2pack(v.x, v.y), h2pack(v.z, v.w));
    *(uint2*)(dst + f) = u;
}

// ================= fp16 GEMM: out[r,o] = sum_c A[r,c] * W[o,c] =================
// Block 128x128, BK=16, 256 threads (8 warps 4x2, warp tile 32x64).
// Fragment-order smem (m16n8k16): A-frag LDS.128, B-frag LDS.64; double buffered.
// A-frag u32 (m,k2=k/2): mtile=m>>4: mtile*128 + ((m&7)*4 + (k2&3))*4 + (k2>>2)*2 + ((m>>3)&1)
// B-frag u32 (n,k2):     ntile=n>>3: ntile*64 + ((n&7)*4 + (k2&3))*2 + (k2>>2)
// dst_mode: 0->g_q fp32, 1->g_k fp32, 2->g_vh fp16 (scatter [b,h,t,d]), 3->Oext fp32
__global__ __launch_bounds__(256) void h16gemm(const __half* __restrict__ A,
                                               const __half* __restrict__ W,
                                               float* __restrict__ Oext,
                                               int dst_mode)
{
    __shared__ unsigned sA[2][1024];
    __shared__ unsigned sB[2][1024];

    int bm = blockIdx.y * 128;
    int bn = blockIdx.x * 128;
    int tid = threadIdx.x;
    int lane = tid & 31;
    int wid = tid >> 5;
    int g = lane >> 2;
    int tg = lane & 3;

    int lr = tid & 127;         // staged row
    int half_sel = tid >> 7;    // 0: A, 1: B

    const unsigned* src = half_sel
        ? (const unsigned*)(W + (size_t)(bn + lr) * Cv)
        : (const unsigned*)(A + (size_t)(bm + lr) * Cv);

    // staging scatter offsets for the 8 u32 of one row-chunk
    int soff[8];
#pragma unroll
    for (int j = 0; j < 8; j++) {
        if (half_sel == 0)
            soff[j] = (lr >> 4) * 128 + ((lr & 7) * 4 + (j & 3)) * 4 + (j >> 2) * 2
                    + ((lr >> 3) & 1);
        else
            soff[j] = (lr >> 3) * 64 + ((lr & 7) * 4 + (j & 3)) * 2 + (j >> 2);
    }
    unsigned* dstbuf[2] = { half_sel ? sB[0] : sA[0], half_sel ? sB[1] : sA[1] };

    int mt0 = (wid & 3) * 2;
    int nt0 = (wid >> 2) * 8;

    float c[2][8][4];
#pragma unroll
    for (int i = 0; i < 2; i++)
#pragma unroll
        for (int j = 0; j < 8; j++)
#pragma unroll
            for (int e = 0; e < 4; e++) c[i][j][e] = 0.0f;

    // prologue
    {
        uint4 v0 = *(const uint4*)(src);
        uint4 v1 = *(const uint4*)(src + 4);
        unsigned vals[8] = { v0.x, v0.y, v0.z, v0.w, v1.x, v1.y, v1.z, v1.w };
#pragma unroll
        for (int j = 0; j < 8; j++) dstbuf[0][soff[j]] = vals[j];
    }
    __syncthreads();

    const int NIT = Cv / 16;   // 128
    for (int it = 0; it < NIT; it++) {
        uint4 v0, v1;
        if (it + 1 < NIT) {
            v0 = *(const uint4*)(src + (it + 1) * 8);
            v1 = *(const uint4*)(src + (it + 1) * 8 + 4);
        }

        const unsigned* SA = sA[it & 1];
        const unsigned* SB = sB[it & 1];
        uint4 a0 = *(const uint4*)&SA[mt0 * 128 + lane * 4];
        uint4 a1 = *(const uint4*)&SA[(mt0 + 1) * 128 + lane * 4];
#pragma unroll
        for (int j = 0; j < 8; j++) {
            uint2 b = *(const uint2*)&SB[(nt0 + j) * 64 + lane * 2];
            mma16816(c[0][j], a0, b);
            mma16816(c[1][j], a1, b);
        }
        __syncthreads();

        if (it + 1 < NIT) {
            unsigned* D = dstbuf[(it + 1) & 1];
            unsigned vals[8] = { v0.x, v0.y, v0.z, v0.w, v1.x, v1.y, v1.z, v1.w };
#pragma unroll
            for (int j = 0; j < 8; j++) D[soff[j]] = vals[j];
            __syncthreads();
        }
    }

    int wm = (wid & 3) * 32;
    int wn = (wid >> 2) * 64;

    if (dst_mode == 3) {
#pragma unroll
        for (int i = 0; i < 2; i++)
#pragma unroll
            for (int j = 0; j < 8; j++) {
                int r = bm + wm + i * 16 + g;
                int o = bn + wn + j * 8 + tg * 2;
                *(float2*)&Oext[(size_t)r * Cv + o] = make_float2(c[i][j][0], c[i][j][1]);
                *(float2*)&Oext[(size_t)(r + 8) * Cv + o] = make_float2(c[i][j][2], c[i][j][3]);
            }
    } else if (dst_mode == 2) {
#pragma unroll
        for (int i = 0; i < 2; i++)
#pragma unroll
            for (int j = 0; j < 8; j++) {
                int r = bm + wm + i * 16 + g;
                int o = bn + wn + j * 8 + tg * 2;
                int b_ = r >> 11, t = r & 2047;
                int h = o >> 7, d = o & 127;
                size_t off = (((size_t)(b_ * Hv + h) * Tv) + t) * HDv + d;
                *(unsigned*)&g_vh[off] = h2pack(c[i][j][0], c[i][j][1]);
                *(unsigned*)&g_vh[off + (size_t)8 * HDv] = h2pack(c[i][j][2], c[i][j][3]);
            }
    } else {
        float* outp = (dst_mode == 0) ? g_q : g_k;
#pragma unroll
        for (int i = 0; i < 2; i++)
#pragma unroll
            for (int j = 0; j < 8; j++) {
                int r = bm + wm + i * 16 + g;
                int o = bn + wn + j * 8 + tg * 2;
                int b_ = r >> 11, t = r & 2047;
                int h = o >> 7, d = o & 127;
                size_t off = (((size_t)(b_ * Hv + h) * Tv) + t) * HDv + d;
                *(float2*)&outp[off] = make_float2(c[i][j][0], c[i][j][1]);
                *(float2*)&outp[off + (size_t)8 * HDv] = make_float2(c[i][j][2], c[i][j][3]);
            }
    }
}

// ---------------- RoPE: fp32 g_q/g_k -> fp16 g_qh/g_kh (scale folded into q) ----------------
__global__ void rope_kernel()
{
    int idx = blockIdx.x * blockDim.x + threadIdx.x;
    int i  = idx & 63;
    int t  = (idx >> 6) & 2047;
    int bh = idx >> 17;
    if (bh >= BHv) return;

    float inv = (float)pow(10000.0, -(double)i / 64.0);
    float f = (float)t * inv;
    float c = cosf(f), s = sinf(f);
    const float scale = 0.08838834764831845f;   // 1/sqrt(128)

    size_t base = ((size_t)bh * Tv + t) * HDv;
    float q1 = g_q[base + i], q2 = g_q[base + i + 64];
    g_qh[base + i]      = __float2half((q1 * c - q2 * s) * scale);
    g_qh[base + i + 64] = __float2half((q2 * c + q1 * s) * scale);
    float k1 = g_k[base + i], k2 = g_k[base + i + 64];
    g_kh[base + i]      = __float2half(k1 * c - k2 * s);
    g_kh[base + i + 64] = __float2half(k2 * c + k1 * s);
}

// ================= fp16 flash attention, causal =================
// CTA: 64 q-rows, 4 warps (each one m16 tile; warp-local softmax).
// smem u32: sQ 4096 (A-frag), sK 4096 (B-frag), sV 4096 (B-frag), sP 4x512.
#define ATT_SMEM_U32  (4096 * 3 + 2048)
#define ATT_SMEM_BYTES (ATT_SMEM_U32 * 4)

__global__ __launch_bounds__(128) void attn_kernel()
{
    extern __shared__ unsigned smn[];
    unsigned* sQ = smn;
    unsigned* sK = sQ + 4096;
    unsigned* sV = sK + 4096;
    unsigned* sP = sV + 4096;

    int bh = blockIdx.y;
    int qb = blockIdx.x;
    int q0 = qb * 64;
    int tid = threadIdx.x;
    int lane = tid & 31;
    int w = tid >> 5;
    int g = lane >> 2;
    int tg = lane & 3;
    size_t base = (size_t)bh * Tv * HDv;

    // stage Q: 64 rows x 64 u32-pairs, A-frag order
    for (int i = tid; i < 4096; i += 128) {
        int r = i >> 6;
        int j = i & 63;                  // d-pair index, d = 2j
        unsigned v = ((const unsigned*)&g_qh[base + (size_t)(q0 + r) * HDv])[j];
        int ks = j >> 3, jj = j & 7;
        int addr = (ks * 4 + (r >> 4)) * 128 + ((r & 7) * 4 + (jj & 3)) * 4
                 + (jj >> 2) * 2 + ((r >> 3) & 1);
        sQ[addr] = v;
    }

    float o[16][4];
#pragma unroll
    for (int nt = 0; nt < 16; nt++)
#pragma unroll
        for (int e = 0; e < 4; e++) o[nt][e] = 0.0f;
    float mrow0 = -1e30f, mrow1 = -1e30f;
    float lrow0 = 0.0f,   lrow1 = 0.0f;

    unsigned* Pw = sP + w * 512;
    __half* sVh = (__half*)sV;

    for (int kt = 0; kt <= qb; kt++) {
        __syncthreads();   // protect sK/sV (and sQ first iter)
        int k0 = kt * 64;
        for (int i = tid; i < 4096; i += 128) {
            int r = i >> 6;              // s index
            int j = i & 63;              // d-pair, d = 2j
            unsigned vk = ((const unsigned*)&g_kh[base + (size_t)(k0 + r) * HDv])[j];
            unsigned vv = ((const unsigned*)&g_vh[base + (size_t)(k0 + r) * HDv])[j];
            // K B-frag: n=r (s), k=d
            int ks = j >> 3, jj = j & 7;
            int ak = (ks * 8 + (r >> 3)) * 64 + ((r & 7) * 4 + (jj & 3)) * 2 + (jj >> 2);
            sK[ak] = vk;
            // V B-frag: n=d, k=r (s) -> two 16-bit stores
            int vks = (r >> 4), vtg = (r >> 1) & 3, vkk = (r >> 3) & 1, ve = r & 1;
            int d0 = 2 * j;
            int i0 = vks * 1024 + (d0 >> 3) * 64 + ((d0 & 7) * 4 + vtg) * 2 + vkk;
            int d1 = d0 + 1;
            int i1 = vks * 1024 + (d1 >> 3) * 64 + ((d1 & 7) * 4 + vtg) * 2 + vkk;
            __half2 hv = *(__half2*)&vv;
            sVh[i0 * 2 + ve] = __low2half(hv);
            sVh[i1 * 2 + ve] = __high2half(hv);
        }
        __syncthreads();

        // ---- S = Q K^T (m16 x n64 x k128) ----
        float s[8][4];
#pragma unroll
        for (int nt = 0; nt < 8; nt++)
#pragma unroll
            for (int e = 0; e < 4; e++) s[nt][e] = 0.0f;
#pragma unroll
        for (int ks = 0; ks < 8; ks++) {
            uint4 aq = *(const uint4*)&sQ[(ks * 4 + w) * 128 + lane * 4];
#pragma unroll
            for (int nt = 0; nt < 8; nt++) {
                uint2 bk = *(const uint2*)&sK[(ks * 8 + nt) * 64 + lane * 2];
                mma16816(s[nt], aq, bk);
            }
        }

        // ---- causal mask (scale already folded into Q) ----
        bool diag = (kt == qb);
        int row0 = q0 + w * 16 + g;
        if (diag) {
#pragma unroll
            for (int nt = 0; nt < 8; nt++)
#pragma unroll
                for (int e2 = 0; e2 < 4; e2++) {
                    int col = k0 + nt * 8 + tg * 2 + (e2 & 1);
                    int rr = row0 + (e2 >> 1) * 8;
                    if (col > rr) s[nt][e2] = -1e30f;
                }
        }

        // ---- warp-local row max ----
        float mx0 = -1e30f, mx1 = -1e30f;
#pragma unroll
        for (int nt = 0; nt < 8; nt++) {
            mx0 = fmaxf(mx0, fmaxf(s[nt][0], s[nt][1]));
            mx1 = fmaxf(mx1, fmaxf(s[nt][2], s[nt][3]));
        }
        mx0 = fmaxf(mx0, __shfl_xor_sync(0xffffffffu, mx0, 1));
        mx0 = fmaxf(mx0, __shfl_xor_sync(0xffffffffu, mx0, 2));
        mx1 = fmaxf(mx1, __shfl_xor_sync(0xffffffffu, mx1, 1));
        mx1 = fmaxf(mx1, __shfl_xor_sync(0xffffffffu, mx1, 2));

        float mn0 = fmaxf(mrow0, mx0);
        float mn1 = fmaxf(mrow1, mx1);
        float al0 = __expf(mrow0 - mn0);
        float al1 = __expf(mrow1 - mn1);
        mrow0 = mn0; mrow1 = mn1;

        // ---- p = exp(s-m), sums, pack to sP (A-frag, half2) ----
        float rs0 = 0.0f, rs1 = 0.0f;
#pragma unroll
        for (int nt = 0; nt < 8; nt++) {
            float p0 = __expf(s[nt][0] - mn0);
            float p1 = __expf(s[nt][1] - mn0);
            float p2 = __expf(s[nt][2] - mn1);
            float p3 = __expf(s[nt][3] - mn1);
            rs0 += p0 + p1; rs1 += p2 + p3;
            int kstep = nt >> 1, kk = nt & 1;
            int addr = kstep * 128 + (g * 4 + tg) * 4 + kk * 2;
            Pw[addr]     = h2pack(p0, p1);   // row g
            Pw[addr + 1] = h2pack(p2, p3);   // row g+8
        }
        rs0 += __shfl_xor_sync(0xffffffffu, rs0, 1);
        rs0 += __shfl_xor_sync(0xffffffffu, rs0, 2);
        rs1 += __shfl_xor_sync(0xffffffffu, rs1, 1);
        rs1 += __shfl_xor_sync(0xffffffffu, rs1, 2);
        lrow0 = lrow0 * al0 + rs0;
        lrow1 = lrow1 * al1 + rs1;

#pragma unroll
        for (int nt = 0; nt < 16; nt++) {
            o[nt][0] *= al0; o[nt][1] *= al0;
            o[nt][2] *= al1; o[nt][3] *= al1;
        }
        __syncwarp();

        // ---- O += P @ V ----
#pragma unroll
        for (int ks = 0; ks < 4; ks++) {
            uint4 ap = *(const uint4*)&Pw[ks * 128 + lane * 4];
#pragma unroll
            for (int nt = 0; nt < 16; nt++) {
                uint2 bv = *(const uint2*)&sV[ks * 1024 + nt * 64 + lane * 2];
                mma16816(o[nt], ap, bv);
            }
        }
    }

    // ---- epilogue -> g_yh fp16 [b,t,c] ----
    int b = bh >> 4;
    int hh = bh & 15;
#pragma unroll
    for (int h = 0; h < 2; h++) {
        float invl = 1.0f / (h ? lrow1 : lrow0);
        int t = q0 + w * 16 + g + h * 8;
        __half* op = g_yh + ((size_t)(b * Tv + t)) * Cv + hh * HDv;
#pragma unroll
        for (int nt = 0; nt < 16; nt++) {
            int d = nt * 8 + tg * 2;
            *(unsigned*)&op[d] = h2pack(o[nt][2 * h] * invl, o[nt][2 * h + 1] * invl);
        }
    }
}

// ---------------- launch ----------------
extern "C" void kernel_launch(void* const* d_in, const int* in_sizes, int n_in,
                              void* d_out, int out_size)
{
    const float* x  = (const float*)d_in[0];
    const float* wq = (const float*)d_in[2];
    const float* wk = (const float*)d_in[3];
    const float* wv = (const float*)d_in[4];
    const float* wo = (const float*)d_in[5];
    float* out = (float*)d_out;

    const size_t NX = (size_t)Bv * Tv * Cv;
    const size_t NW = (size_t)Cv * Cv;

    cvt_kernel<<<NX / 1024, 256>>>(x, 0, 0);
    cvt_kernel<<<NW / 1024, 256>>>(wq, 1, 0 * NW);
    cvt_kernel<<<NW / 1024, 256>>>(wk, 1, 1 * NW);
    cvt_kernel<<<NW / 1024, 256>>>(wv, 1, 2 * NW);
    cvt_kernel<<<NW / 1024, 256>>>(wo, 1, 3 * NW);

    static __half* whp = nullptr;
    static __half* xhp = nullptr;
    static __half* yhp = nullptr;
    if (!whp) {
        cudaGetSymbolAddress((void**)&whp, g_wh);
        cudaGetSymbolAddress((void**)&xhp, g_xh);
        cudaGetSymbolAddress((void**)&yhp, g_yh);
        cudaFuncSetAttribute(attn_kernel, cudaFuncAttributeMaxDynamicSharedMemorySize,
                             ATT_SMEM_BYTES);
    }

    dim3 gg(Cv / 128, (Bv * Tv) / 128);  // (16, 64)

    h16gemm<<<gg, 256>>>(xhp, whp + 0 * NW, nullptr, 0);
    h16gemm<<<gg, 256>>>(xhp, whp + 1 * NW, nullptr, 1);
    h16gemm<<<gg, 256>>>(xhp, whp + 2 * NW, nullptr, 2);

    rope_kernel<<<(BHv * Tv * 64) / 256, 256>>>();

    attn_kernel<<<dim3(Tv / 64, BHv), 128, ATT_SMEM_BYTES>>>();

    h16gemm<<<gg, 256>>>(yhp, whp + 3 * NW, out, 3);
}

// round 7
// speedup vs baseline: 1.7534x; 1.7534x over previous
#include <cuda_runtime.h>
#include <cuda_fp16.h>
#include <math.h>
#include <stdint.h>

#define Bv  4
#define Tv  2048
#define Cv  2048
#define Hv  16
#define HDv 128
#define BHv (Bv*Hv)

// ---------------- scratch (device globals; no allocation allowed) ----------------
__device__ float  g_q [(size_t)BHv * Tv * HDv];    // fp32 Q (pre-rope) -> tf32 bits
__device__ float  g_k [(size_t)BHv * Tv * HDv];
__device__ float  g_v [(size_t)BHv * Tv * HDv];    // tf32 bits
__device__ __half g_yh[(size_t)Bv * Tv * Cv];      // attention out (fp16)
__device__ __half g_xh[(size_t)Bv * Tv * Cv];      // x in fp16
__device__ __half g_wh[(size_t)4 * Cv * Cv];       // wq,wk,wv,wo in fp16

__device__ __forceinline__ unsigned f2tf(float f) {
    unsigned u;
    asm("cvt.rna.tf32.f32 %0, %1;" : "=r"(u) : "f"(f));
    return u;
}
__device__ __forceinline__ unsigned h2pack(float a, float b) {
    __half2 h = __floats2half2_rn(a, b);
    return *(unsigned*)&h;
}
__device__ __forceinline__ uint32_t smem_u32(const void* p) {
    uint32_t a;
    asm("{ .reg .u64 t; cvta.to.shared.u64 t, %1; cvt.u32.u64 %0, t; }" : "=r"(a) : "l"(p));
    return a;
}

__device__ __forceinline__ void mma_h(float* c, unsigned a0, unsigned a1, unsigned a2,
                                      unsigned a3, unsigned b0, unsigned b1) {
    asm volatile(
        "mma.sync.aligned.m16n8k16.row.col.f32.f16.f16.f32 "
        "{%0,%1,%2,%3}, {%4,%5,%6,%7}, {%8,%9}, {%0,%1,%2,%3};\n"
        : "+f"(c[0]), "+f"(c[1]), "+f"(c[2]), "+f"(c[3])
        : "r"(a0), "r"(a1), "r"(a2), "r"(a3), "r"(b0), "r"(b1));
}
__device__ __forceinline__ void mma_tf(float* c, const uint4& a, const uint2& b) {
    asm volatile(
        "mma.sync.aligned.m16n8k8.row.col.f32.tf32.tf32.f32 "
        "{%0,%1,%2,%3}, {%4,%5,%6,%7}, {%8,%9}, {%0,%1,%2,%3};\n"
        : "+f"(c[0]), "+f"(c[1]), "+f"(c[2]), "+f"(c[3])
        : "r"(a.x), "r"(a.y), "r"(a.z), "r"(a.w), "r"(b.x), "r"(b.y));
}

__device__ __forceinline__ void cp16(uint32_t sdst, const void* gsrc) {
    asm volatile("cp.async.cg.shared.global [%0], [%1], 16;" :: "r"(sdst), "l"(gsrc));
}
#define CP_COMMIT() asm volatile("cp.async.commit_group;" ::: "memory")
#define CP_WAIT1()  asm volatile("cp.async.wait_group 1;" ::: "memory")
#define CP_WAIT0()  asm volatile("cp.async.wait_group 0;" ::: "memory")

// 16B-chunk swizzle for tiles with 64B rows (4 chunks/row), 128B lines (2 rows):
// chunk' = (r>>1)*8 + (((r&1)*4 + c) ^ ((r>>1)&7))
__device__ __forceinline__ int sw16(int r, int c) {
    return ((r >> 1) << 3) + ((((r & 1) << 2) + c) ^ ((r >> 1) & 7));
}

__device__ __forceinline__ void ldm4(uint4& v, uint32_t addr) {
    asm volatile("ldmatrix.sync.aligned.m8n8.x4.shared.b16 {%0,%1,%2,%3}, [%4];"
                 : "=r"(v.x), "=r"(v.y), "=r"(v.z), "=r"(v.w) : "r"(addr));
}

// ---------------- pre-convert fp32 -> fp16 ----------------
__global__ void cvt_kernel(const float* __restrict__ src, int dst_sel, size_t dstoff)
{
    size_t f = ((size_t)blockIdx.x * blockDim.x + threadIdx.x) * 4;
    float4 v = *(const float4*)(src + f);
    __half* dst = (dst_sel == 0) ? g_xh : (g_wh + dstoff);
    *(uint2*)(dst + f) = make_uint2(h2pack(v.x, v.y), h2pack(v.z, v.w));
}

// ========== fp16 pipelined GEMM: out[r,o] = sum_c A[r,c] * W[o,c] ==========
// 128x128 tile, BK=32, 256 threads (8 warps 4x2, warp tile 32x64).
// cp.async 3-stage, swizzled row-major smem, ldmatrix.x4 fragments.
// dst_mode: 0->g_q fp32, 1->g_k fp32, 2->g_v tf32 bits (scatter [b,h,t,d]), 3->Oext fp32
#define GEMM_SMEM_BYTES (3 * 16384)

__global__ __launch_bounds__(256, 2) void h16gemm(const __half* __restrict__ A,
                                                  const __half* __restrict__ W,
                                                  float* __restrict__ Oext,
                                                  int dst_mode)
{
    extern __shared__ __align__(1024) char smraw[];
    uint32_t sbase = smem_u32(smraw);

    int tid = threadIdx.x;
    int lane = tid & 31;
    int wid = tid >> 5;
    int g = lane >> 2;
    int tg = lane & 3;
    int bm = blockIdx.y * 128;
    int bn = blockIdx.x * 128;
    int wm = (wid & 3) * 32;
    int wn = (wid >> 2) * 64;

    int r0 = tid >> 2;          // staged chunk row (0..63), +64 for second
    int c0 = tid & 3;           // chunk col
    const __half* gA  = A + (size_t)(bm + r0) * Cv + c0 * 8;
    const __half* gA2 = gA + (size_t)64 * Cv;
    const __half* gB  = W + (size_t)(bn + r0) * Cv + c0 * 8;
    const __half* gB2 = gB + (size_t)64 * Cv;
    uint32_t sA0 = sbase + sw16(r0, c0) * 16;
    uint32_t sA1 = sbase + sw16(r0 + 64, c0) * 16;

    float c[2][8][4];
#pragma unroll
    for (int i = 0; i < 2; i++)
#pragma unroll
        for (int j = 0; j < 8; j++)
#pragma unroll
            for (int e = 0; e < 4; e++) c[i][j][e] = 0.0f;

    const int NIT = Cv / 32;    // 64

#define ISSUE(st) do {                                                  \
        int buf_ = (st) % 3;                                            \
        uint32_t ao_ = buf_ * 16384;                                    \
        size_t ko_ = (size_t)(st) * 32;                                 \
        cp16(sA0 + ao_,        gA  + ko_);                              \
        cp16(sA1 + ao_,        gA2 + ko_);                              \
        cp16(sA0 + ao_ + 8192, gB  + ko_);                              \
        cp16(sA1 + ao_ + 8192, gB2 + ko_);                              \
        CP_COMMIT();                                                    \
    } while (0)

    ISSUE(0);
    ISSUE(1);

    int lrow = lane & 7;
    int sel = lane >> 3;

    for (int it = 0; it < NIT; it++) {
        if (it < NIT - 2) CP_WAIT1(); else CP_WAIT0();
        __syncthreads();

        uint32_t ab = sbase + (it % 3) * 16384;
        uint32_t bb = ab + 8192;
#pragma unroll
        for (int ks = 0; ks < 2; ks++) {
            uint4 a[2];
#pragma unroll
            for (int i = 0; i < 2; i++) {
                int row = wm + i * 16 + ((sel & 1) << 3) + lrow;
                int ch  = 2 * ks + (sel >> 1);
                ldm4(a[i], ab + sw16(row, ch) * 16);
            }
#pragma unroll
            for (int p = 0; p < 4; p++) {
                int row = wn + p * 16 + ((sel >> 1) << 3) + lrow;
                int ch  = 2 * ks + (sel & 1);
                uint4 bv;
                ldm4(bv, bb + sw16(row, ch) * 16);
                mma_h(c[0][2 * p],     a[0].x, a[0].y, a[0].z, a[0].w, bv.x, bv.y);
                mma_h(c[0][2 * p + 1], a[0].x, a[0].y, a[0].z, a[0].w, bv.z, bv.w);
                mma_h(c[1][2 * p],     a[1].x, a[1].y, a[1].z, a[1].w, bv.x, bv.y);
                mma_h(c[1][2 * p + 1], a[1].x, a[1].y, a[1].z, a[1].w, bv.z, bv.w);
            }
        }
        if (it + 2 < NIT) ISSUE(it + 2);
    }

    // ---- epilogue ----
    if (dst_mode == 3) {
#pragma unroll
        for (int i = 0; i < 2; i++)
#pragma unroll
            for (int j = 0; j < 8; j++) {
                int r = bm + wm + i * 16 + g;
                int o = bn + wn + j * 8 + tg * 2;
                *(float2*)&Oext[(size_t)r * Cv + o] = make_float2(c[i][j][0], c[i][j][1]);
                *(float2*)&Oext[(size_t)(r + 8) * Cv + o] = make_float2(c[i][j][2], c[i][j][3]);
            }
    } else {
        float* outp = (dst_mode == 0) ? g_q : (dst_mode == 1) ? g_k : g_v;
        bool cvv = (dst_mode == 2);
#pragma unroll
        for (int i = 0; i < 2; i++)
#pragma unroll
            for (int j = 0; j < 8; j++) {
                int r = bm + wm + i * 16 + g;
                int o = bn + wn + j * 8 + tg * 2;
                int b_ = r >> 11, t = r & 2047;
                int h = o >> 7, d = o & 127;
                size_t off = (((size_t)(b_ * Hv + h) * Tv) + t) * HDv + d;
                float v0 = c[i][j][0], v1 = c[i][j][1], v2 = c[i][j][2], v3 = c[i][j][3];
                if (cvv) {
                    v0 = __uint_as_float(f2tf(v0)); v1 = __uint_as_float(f2tf(v1));
                    v2 = __uint_as_float(f2tf(v2)); v3 = __uint_as_float(f2tf(v3));
                }
                *(float2*)&outp[off] = make_float2(v0, v1);
                *(float2*)&outp[off + (size_t)8 * HDv] = make_float2(v2, v3);
            }
    }
#undef ISSUE
}

// ---------------- RoPE: fp32 -> tf32 bits in place ----------------
__global__ void rope_kernel()
{
    int idx = blockIdx.x * blockDim.x + threadIdx.x;
    int i  = idx & 63;
    int t  = (idx >> 6) & 2047;
    int bh = idx >> 17;
    if (bh >= BHv) return;

    float inv = (float)pow(10000.0, -(double)i / 64.0);
    float f = (float)t * inv;
    float c = cosf(f), s = sinf(f);

    size_t base = ((size_t)bh * Tv + t) * HDv;
    float q1 = g_q[base + i], q2 = g_q[base + i + 64];
    g_q[base + i]      = __uint_as_float(f2tf(q1 * c - q2 * s));
    g_q[base + i + 64] = __uint_as_float(f2tf(q2 * c + q1 * s));
    float k1 = g_k[base + i], k2 = g_k[base + i + 64];
    g_k[base + i]      = __uint_as_float(f2tf(k1 * c - k2 * s));
    g_k[base + i + 64] = __uint_as_float(f2tf(k2 * c + k1 * s));
}

// ================= TF32 flash attention (R4-proven), causal =================
#define ATT_SMEM_U32  (8192 * 3 + 4096)
#define ATT_SMEM_BYTES (ATT_SMEM_U32 * 4)

__global__ __launch_bounds__(128) void attn_kernel()
{
    extern __shared__ unsigned smn[];
    unsigned* sQ = smn;
    unsigned* sK = sQ + 8192;
    unsigned* sV = sK + 8192;
    unsigned* sP = sV + 8192;

    int bh = blockIdx.y;
    int qb = blockIdx.x;
    int q0 = qb * 64;
    int tid = threadIdx.x;
    int lane = tid & 31;
    int w = tid >> 5;
    int g = lane >> 2;
    int tg = lane & 3;
    size_t base = (size_t)bh * Tv * HDv;

    for (int i = tid; i < 2048; i += 128) {
        int r  = i >> 5;
        int d0 = (i & 31) * 4;
        uint4 v = *(const uint4*)&g_q[base + (size_t)(q0 + r) * HDv + d0];
        int addr = ((d0 >> 3) * 4 + (r >> 4)) * 128 + (r & 7) * 16
                 + (((r >> 3) & 1) | (((d0 >> 2) & 1) << 1));
        sQ[addr + 0] = v.x; sQ[addr + 4]  = v.y;
        sQ[addr + 8] = v.z; sQ[addr + 12] = v.w;
    }

    float o[16][4];
#pragma unroll
    for (int nt = 0; nt < 16; nt++)
#pragma unroll
        for (int e = 0; e < 4; e++) o[nt][e] = 0.0f;
    float mrow0 = -1e30f, mrow1 = -1e30f;
    float lrow0 = 0.0f,   lrow1 = 0.0f;

    const float scale = 0.08838834764831845f;
    unsigned* Pw = sP + w * 1024;

    for (int kt = 0; kt <= qb; kt++) {
        __syncthreads();
        int k0 = kt * 64;
        for (int i = tid; i < 2048; i += 128) {
            int r  = i >> 5;
            int d0 = (i & 31) * 4;
            uint4 vk = *(const uint4*)&g_k[base + (size_t)(k0 + r) * HDv + d0];
            uint4 vv = *(const uint4*)&g_v[base + (size_t)(k0 + r) * HDv + d0];
            int ak = ((d0 >> 3) * 8 + (r >> 3)) * 64 + (r & 7) * 8 + ((d0 >> 2) & 1);
            sK[ak + 0] = vk.x; sK[ak + 2] = vk.y;
            sK[ak + 4] = vk.z; sK[ak + 6] = vk.w;
            int av = ((r >> 3) * 16 + (d0 >> 3)) * 64 + ((d0 & 7) * 4 + (r & 3)) * 2
                   + ((r >> 2) & 1);
            sV[av + 0]  = vv.x; sV[av + 8]  = vv.y;
            sV[av + 16] = vv.z; sV[av + 24] = vv.w;
        }
        __syncthreads();

        float s[8][4];
#pragma unroll
        for (int nt = 0; nt < 8; nt++)
#pragma unroll
            for (int e = 0; e < 4; e++) s[nt][e] = 0.0f;
#pragma unroll
        for (int ks = 0; ks < 16; ks++) {
            uint4 aq = *(const uint4*)&sQ[(ks * 4 + w) * 128 + lane * 4];
#pragma unroll
            for (int nt = 0; nt < 8; nt++) {
                uint2 bk = *(const uint2*)&sK[(ks * 8 + nt) * 64 + lane * 2];
                mma_tf(s[nt], aq, bk);
            }
        }

        bool diag = (kt == qb);
        int row0 = q0 + w * 16 + g;
#pragma unroll
        for (int nt = 0; nt < 8; nt++) {
#pragma unroll
            for (int e2 = 0; e2 < 4; e2++) {
                float v = s[nt][e2] * scale;
                if (diag) {
                    int col = k0 + nt * 8 + tg * 2 + (e2 & 1);
                    int rr = row0 + (e2 >> 1) * 8;
                    if (col > rr) v = -1e30f;
                }
                s[nt][e2] = v;
            }
        }

        float mx0 = -1e30f, mx1 = -1e30f;
#pragma unroll
        for (int nt = 0; nt < 8; nt++) {
            mx0 = fmaxf(mx0, fmaxf(s[nt][0], s[nt][1]));
            mx1 = fmaxf(mx1, fmaxf(s[nt][2], s[nt][3]));
        }
        mx0 = fmaxf(mx0, __shfl_xor_sync(0xffffffffu, mx0, 1));
        mx0 = fmaxf(mx0, __shfl_xor_sync(0xffffffffu, mx0, 2));
        mx1 = fmaxf(mx1, __shfl_xor_sync(0xffffffffu, mx1, 1));
        mx1 = fmaxf(mx1, __shfl_xor_sync(0xffffffffu, mx1, 2));

        float mn0 = fmaxf(mrow0, mx0);
        float mn1 = fmaxf(mrow1, mx1);
        float al0 = __expf(mrow0 - mn0);
        float al1 = __expf(mrow1 - mn1);
        mrow0 = mn0; mrow1 = mn1;

        float rs0 = 0.0f, rs1 = 0.0f;
#pragma unroll
        for (int nt = 0; nt < 8; nt++) {
            float p0 = __expf(s[nt][0] - mn0);
            float p1 = __expf(s[nt][1] - mn0);
            float p2 = __expf(s[nt][2] - mn1);
            float p3 = __expf(s[nt][3] - mn1);
            rs0 += p0 + p1; rs1 += p2 + p3;
            s[nt][0] = p0; s[nt][1] = p1; s[nt][2] = p2; s[nt][3] = p3;
        }
        rs0 += __shfl_xor_sync(0xffffffffu, rs0, 1);
        rs0 += __shfl_xor_sync(0xffffffffu, rs0, 2);
        rs1 += __shfl_xor_sync(0xffffffffu, rs1, 1);
        rs1 += __shfl_xor_sync(0xffffffffu, rs1, 2);
        lrow0 = lrow0 * al0 + rs0;
        lrow1 = lrow1 * al1 + rs1;

#pragma unroll
        for (int nt = 0; nt < 16; nt++) {
            o[nt][0] *= al0; o[nt][1] *= al0;
            o[nt][2] *= al1; o[nt][3] *= al1;
        }

#pragma unroll
        for (int nt = 0; nt < 8; nt++) {
#pragma unroll
            for (int e2 = 0; e2 < 4; e2++) {
                int e = e2 & 1, h = e2 >> 1;
                int ss = tg * 2 + e;
                int addr = nt * 128 + (g * 4 + (ss & 3)) * 4
                         + (((ss >> 2) << 1) | h);
                Pw[addr] = f2tf(s[nt][e2]);
            }
        }
        __syncwarp();

#pragma unroll
        for (int ks = 0; ks < 8; ks++) {
            uint4 ap = *(const uint4*)&Pw[ks * 128 + lane * 4];
#pragma unroll
            for (int nt = 0; nt < 16; nt++) {
                uint2 bv = *(const uint2*)&sV[(ks * 16 + nt) * 64 + lane * 2];
                mma_tf(o[nt], ap, bv);
            }
        }
    }

    // ---- epilogue -> g_yh fp16 [b,t,c] ----
    int b = bh >> 4;
    int hh = bh & 15;
#pragma unroll
    for (int h = 0; h < 2; h++) {
        float invl = 1.0f / (h ? lrow1 : lrow0);
        int t = q0 + w * 16 + g + h * 8;
        __half* op = g_yh + ((size_t)(b * Tv + t)) * Cv + hh * HDv;
#pragma unroll
        for (int nt = 0; nt < 16; nt++) {
            int d = nt * 8 + tg * 2;
            *(unsigned*)&op[d] = h2pack(o[nt][2 * h] * invl, o[nt][2 * h + 1] * invl);
        }
    }
}

// ---------------- launch ----------------
extern "C" void kernel_launch(void* const* d_in, const int* in_sizes, int n_in,
                              void* d_out, int out_size)
{
    const float* x  = (const float*)d_in[0];
    const float* wq = (const float*)d_in[2];
    const float* wk = (const float*)d_in[3];
    const float* wv = (const float*)d_in[4];
    const float* wo = (const float*)d_in[5];
    float* out = (float*)d_out;

    const size_t NX = (size_t)Bv * Tv * Cv;
    const size_t NW = (size_t)Cv * Cv;

    cvt_kernel<<<NX / 1024, 256>>>(x, 0, 0);
    cvt_kernel<<<NW / 1024, 256>>>(wq, 1, 0 * NW);
    cvt_kernel<<<NW / 1024, 256>>>(wk, 1, 1 * NW);
    cvt_kernel<<<NW / 1024, 256>>>(wv, 1, 2 * NW);
    cvt_kernel<<<NW / 1024, 256>>>(wo, 1, 3 * NW);

    static __half* whp = nullptr;
    static __half* xhp = nullptr;
    static __half* yhp = nullptr;
    if (!whp) {
        cudaGetSymbolAddress((void**)&whp, g_wh);
        cudaGetSymbolAddress((void**)&xhp, g_xh);
        cudaGetSymbolAddress((void**)&yhp, g_yh);
        cudaFuncSetAttribute(h16gemm, cudaFuncAttributeMaxDynamicSharedMemorySize,
                             GEMM_SMEM_BYTES);
        cudaFuncSetAttribute(attn_kernel, cudaFuncAttributeMaxDynamicSharedMemorySize,
                             ATT_SMEM_BYTES);
    }

    dim3 gg(Cv / 128, (Bv * Tv) / 128);  // (16, 64)

    h16gemm<<<gg, 256, GEMM_SMEM_BYTES>>>(xhp, whp + 0 * NW, nullptr, 0);
    h16gemm<<<gg, 256, GEMM_SMEM_BYTES>>>(xhp, whp + 1 * NW, nullptr, 1);
    h16gemm<<<gg, 256, GEMM_SMEM_BYTES>>>(xhp, whp + 2 * NW, nullptr, 2);

    rope_kernel<<<(BHv * Tv * 64) / 256, 256>>>();

    attn_kernel<<<dim3(Tv / 64, BHv), 128, ATT_SMEM_BYTES>>>();

    h16gemm<<<gg, 256, GEMM_SMEM_BYTES>>>(yhp, whp + 3 * NW, out, 3);
}

// round 8
// speedup vs baseline: 3.2233x; 1.8383x over previous
#include <cuda_runtime.h>
#include <cuda_fp16.h>
#include <math.h>
#include <stdint.h>

#define Bv  4
#define Tv  2048
#define Cv  2048
#define Hv  16
#define HDv 128
#define BHv (Bv*Hv)

// ---------------- scratch (device globals; no allocation allowed) ----------------
__device__ float  g_q [(size_t)BHv * Tv * HDv];    // fp32 Q (pre-rope)
__device__ float  g_k [(size_t)BHv * Tv * HDv];
__device__ __half g_qh[(size_t)BHv * Tv * HDv];    // fp16 post-rope (scale folded in Q)
__device__ __half g_kh[(size_t)BHv * Tv * HDv];
__device__ __half g_vh[(size_t)BHv * Tv * HDv];
__device__ __half g_yh[(size_t)Bv * Tv * Cv];      // attention out (fp16)
__device__ __half g_xh[(size_t)Bv * Tv * Cv];      // x in fp16
__device__ __half g_wh[(size_t)4 * Cv * Cv];       // wq,wk,wv,wo in fp16

__device__ __forceinline__ unsigned h2pack(float a, float b) {
    __half2 h = __floats2half2_rn(a, b);
    return *(unsigned*)&h;
}
__device__ __forceinline__ uint32_t smem_u32(const void* p) {
    uint32_t a;
    asm("{ .reg .u64 t; cvta.to.shared.u64 t, %1; cvt.u32.u64 %0, t; }" : "=r"(a) : "l"(p));
    return a;
}
__device__ __forceinline__ void mma_h(float* c, unsigned a0, unsigned a1, unsigned a2,
                                      unsigned a3, unsigned b0, unsigned b1) {
    asm volatile(
        "mma.sync.aligned.m16n8k16.row.col.f32.f16.f16.f32 "
        "{%0,%1,%2,%3}, {%4,%5,%6,%7}, {%8,%9}, {%0,%1,%2,%3};\n"
        : "+f"(c[0]), "+f"(c[1]), "+f"(c[2]), "+f"(c[3])
        : "r"(a0), "r"(a1), "r"(a2), "r"(a3), "r"(b0), "r"(b1));
}
__device__ __forceinline__ void cp16(uint32_t sdst, const void* gsrc) {
    asm volatile("cp.async.cg.shared.global [%0], [%1], 16;" :: "r"(sdst), "l"(gsrc));
}
#define CP_COMMIT() asm volatile("cp.async.commit_group;" ::: "memory")
#define CP_WAIT1()  asm volatile("cp.async.wait_group 1;" ::: "memory")
#define CP_WAIT0()  asm volatile("cp.async.wait_group 0;" ::: "memory")

__device__ __forceinline__ void ldm4(uint4& v, uint32_t addr) {
    asm volatile("ldmatrix.sync.aligned.m8n8.x4.shared.b16 {%0,%1,%2,%3}, [%4];"
                 : "=r"(v.x), "=r"(v.y), "=r"(v.z), "=r"(v.w) : "r"(addr));
}
__device__ __forceinline__ void ldm4t(uint4& v, uint32_t addr) {
    asm volatile("ldmatrix.sync.aligned.m8n8.x4.trans.shared.b16 {%0,%1,%2,%3}, [%4];"
                 : "=r"(v.x), "=r"(v.y), "=r"(v.z), "=r"(v.w) : "r"(addr));
}

// 64B-row tiles (GEMM): chunk' = (r>>1)*8 + (((r&1)*4 + c) ^ ((r>>1)&7))
__device__ __forceinline__ int sw16(int r, int c) {
    return ((r >> 1) << 3) + ((((r & 1) << 2) + c) ^ ((r >> 1) & 7));
}
// 256B-row tiles (attention, 16 chunks/row): byte addr
__device__ __forceinline__ uint32_t sw256(int r, int c) {
    return (uint32_t)(r * 256 + ((c ^ (r & 7)) << 4));
}

// ---------------- pre-convert fp32 -> fp16 ----------------
__global__ void cvt_kernel(const float* __restrict__ src, int dst_sel, size_t dstoff)
{
    size_t f = ((size_t)blockIdx.x * blockDim.x + threadIdx.x) * 4;
    float4 v = *(const float4*)(src + f);
    __half* dst = (dst_sel == 0) ? g_xh : (g_wh + dstoff);
    *(uint2*)(dst + f) = make_uint2(h2pack(v.x, v.y), h2pack(v.z, v.w));
}

// ========== fp16 pipelined GEMM (R7-proven): out[r,o] = sum_c A[r,c]*W[o,c] ==========
// dst_mode: 0->g_q fp32, 1->g_k fp32, 2->g_vh fp16 (scatter [b,h,t,d]), 3->Oext fp32
#define GEMM_SMEM_BYTES (3 * 16384)

__global__ __launch_bounds__(256, 2) void h16gemm(const __half* __restrict__ A,
                                                  const __half* __restrict__ W,
                                                  float* __restrict__ Oext,
                                                  int dst_mode)
{
    extern __shared__ __align__(1024) char smraw[];
    uint32_t sbase = smem_u32(smraw);

    int tid = threadIdx.x;
    int lane = tid & 31;
    int wid = tid >> 5;
    int g = lane >> 2;
    int tg = lane & 3;
    int bm = blockIdx.y * 128;
    int bn = blockIdx.x * 128;
    int wm = (wid & 3) * 32;
    int wn = (wid >> 2) * 64;

    int r0 = tid >> 2;
    int c0 = tid & 3;
    const __half* gA  = A + (size_t)(bm + r0) * Cv + c0 * 8;
    const __half* gA2 = gA + (size_t)64 * Cv;
    const __half* gB  = W + (size_t)(bn + r0) * Cv + c0 * 8;
    const __half* gB2 = gB + (size_t)64 * Cv;
    uint32_t sA0 = sbase + sw16(r0, c0) * 16;
    uint32_t sA1 = sbase + sw16(r0 + 64, c0) * 16;

    float c[2][8][4];
#pragma unroll
    for (int i = 0; i < 2; i++)
#pragma unroll
        for (int j = 0; j < 8; j++)
#pragma unroll
            for (int e = 0; e < 4; e++) c[i][j][e] = 0.0f;

    const int NIT = Cv / 32;

#define ISSUE(st) do {                                                  \
        uint32_t ao_ = ((st) % 3) * 16384;                              \
        size_t ko_ = (size_t)(st) * 32;                                 \
        cp16(sA0 + ao_,        gA  + ko_);                              \
        cp16(sA1 + ao_,        gA2 + ko_);                              \
        cp16(sA0 + ao_ + 8192, gB  + ko_);                              \
        cp16(sA1 + ao_ + 8192, gB2 + ko_);                              \
        CP_COMMIT();                                                    \
    } while (0)

    ISSUE(0);
    ISSUE(1);

    int lrow = lane & 7;
    int sel = lane >> 3;

    for (int it = 0; it < NIT; it++) {
        if (it < NIT - 2) CP_WAIT1(); else CP_WAIT0();
        __syncthreads();

        uint32_t ab = sbase + (it % 3) * 16384;
        uint32_t bb = ab + 8192;
#pragma unroll
        for (int ks = 0; ks < 2; ks++) {
            uint4 a[2];
#pragma unroll
            for (int i = 0; i < 2; i++) {
                int row = wm + i * 16 + ((sel & 1) << 3) + lrow;
                int ch  = 2 * ks + (sel >> 1);
                ldm4(a[i], ab + sw16(row, ch) * 16);
            }
#pragma unroll
            for (int p = 0; p < 4; p++) {
                int row = wn + p * 16 + ((sel >> 1) << 3) + lrow;
                int ch  = 2 * ks + (sel & 1);
                uint4 bv;
                ldm4(bv, bb + sw16(row, ch) * 16);
                mma_h(c[0][2 * p],     a[0].x, a[0].y, a[0].z, a[0].w, bv.x, bv.y);
                mma_h(c[0][2 * p + 1], a[0].x, a[0].y, a[0].z, a[0].w, bv.z, bv.w);
                mma_h(c[1][2 * p],     a[1].x, a[1].y, a[1].z, a[1].w, bv.x, bv.y);
                mma_h(c[1][2 * p + 1], a[1].x, a[1].y, a[1].z, a[1].w, bv.z, bv.w);
            }
        }
        if (it + 2 < NIT) ISSUE(it + 2);
    }
#undef ISSUE

    if (dst_mode == 3) {
#pragma unroll
        for (int i = 0; i < 2; i++)
#pragma unroll
            for (int j = 0; j < 8; j++) {
                int r = bm + wm + i * 16 + g;
                int o = bn + wn + j * 8 + tg * 2;
                *(float2*)&Oext[(size_t)r * Cv + o] = make_float2(c[i][j][0], c[i][j][1]);
                *(float2*)&Oext[(size_t)(r + 8) * Cv + o] = make_float2(c[i][j][2], c[i][j][3]);
            }
    } else if (dst_mode == 2) {
#pragma unroll
        for (int i = 0; i < 2; i++)
#pragma unroll
            for (int j = 0; j < 8; j++) {
                int r = bm + wm + i * 16 + g;
                int o = bn + wn + j * 8 + tg * 2;
                int b_ = r >> 11, t = r & 2047;
                int h = o >> 7, d = o & 127;
                size_t off = (((size_t)(b_ * Hv + h) * Tv) + t) * HDv + d;
                *(unsigned*)&g_vh[off] = h2pack(c[i][j][0], c[i][j][1]);
                *(unsigned*)&g_vh[off + (size_t)8 * HDv] = h2pack(c[i][j][2], c[i][j][3]);
            }
    } else {
        float* outp = (dst_mode == 0) ? g_q : g_k;
#pragma unroll
        for (int i = 0; i < 2; i++)
#pragma unroll
            for (int j = 0; j < 8; j++) {
                int r = bm + wm + i * 16 + g;
                int o = bn + wn + j * 8 + tg * 2;
                int b_ = r >> 11, t = r & 2047;
                int h = o >> 7, d = o & 127;
                size_t off = (((size_t)(b_ * Hv + h) * Tv) + t) * HDv + d;
                *(float2*)&outp[off] = make_float2(c[i][j][0], c[i][j][1]);
                *(float2*)&outp[off + (size_t)8 * HDv] = make_float2(c[i][j][2], c[i][j][3]);
            }
    }
}

// ---------------- RoPE: fp32 -> fp16 (scale folded into Q) ----------------
__global__ void rope_kernel()
{
    int idx = blockIdx.x * blockDim.x + threadIdx.x;
    int i  = idx & 63;
    int t  = (idx >> 6) & 2047;
    int bh = idx >> 17;
    if (bh >= BHv) return;

    float inv = (float)pow(10000.0, -(double)i / 64.0);
    float f = (float)t * inv;
    float c = cosf(f), s = sinf(f);
    const float scale = 0.08838834764831845f;   // 1/sqrt(128)

    size_t base = ((size_t)bh * Tv + t) * HDv;
    float q1 = g_q[base + i], q2 = g_q[base + i + 64];
    g_qh[base + i]      = __float2half((q1 * c - q2 * s) * scale);
    g_qh[base + i + 64] = __float2half((q2 * c + q1 * s) * scale);
    float k1 = g_k[base + i], k2 = g_k[base + i + 64];
    g_kh[base + i]      = __float2half(k1 * c - k2 * s);
    g_kh[base + i + 64] = __float2half(k2 * c + k1 * s);
}

// ================= fp16 flash attention, cp.async + ldmatrix, causal =================
// CTA: 64 q rows, 128 threads (4 warps, warp = one m16 q-tile; warp-local softmax).
// smem: Q 16KB @0; 3 stages of (K 16KB + V 16KB) @16384 + s*32768. Rows = 256B swizzled.
#define ATT_SMEM_BYTES (16384 + 3 * 32768)

__global__ __launch_bounds__(128) void attn_kernel()
{
    extern __shared__ __align__(1024) char smraw[];
    uint32_t sbase = smem_u32(smraw);

    int bh = blockIdx.y;
    int qb = blockIdx.x;
    int q0 = qb * 64;
    int tid = threadIdx.x;
    int lane = tid & 31;
    int w = tid >> 5;
    int g = lane >> 2;
    int tg = lane & 3;
    int lrow = lane & 7;
    int sel = lane >> 3;
    size_t base = (size_t)bh * Tv * HDv;

#define ISSUE_KV(kt) do {                                                        \
        uint32_t kb_ = sbase + 16384 + ((kt) % 3) * 32768;                       \
        int k0_ = (kt) * 64;                                                     \
        for (int i = tid; i < 1024; i += 128) {                                  \
            int r_ = i >> 4, c_ = i & 15;                                        \
            cp16(kb_ + sw256(r_, c_),         &g_kh[base + (size_t)(k0_ + r_) * HDv + c_ * 8]); \
            cp16(kb_ + 16384 + sw256(r_, c_), &g_vh[base + (size_t)(k0_ + r_) * HDv + c_ * 8]); \
        }                                                                        \
        CP_COMMIT();                                                             \
    } while (0)

    // group 0: Q + KV(0)
    for (int i = tid; i < 1024; i += 128) {
        int r = i >> 4, c = i & 15;
        cp16(sbase + sw256(r, c), &g_qh[base + (size_t)(q0 + r) * HDv + c * 8]);
    }
    {
        uint32_t kb = sbase + 16384;
        for (int i = tid; i < 1024; i += 128) {
            int r = i >> 4, c = i & 15;
            cp16(kb + sw256(r, c),         &g_kh[base + (size_t)r * HDv + c * 8]);
            cp16(kb + 16384 + sw256(r, c), &g_vh[base + (size_t)r * HDv + c * 8]);
        }
        CP_COMMIT();
    }
    if (qb >= 1) ISSUE_KV(1);

    float o[16][4];
#pragma unroll
    for (int nt = 0; nt < 16; nt++)
#pragma unroll
        for (int e = 0; e < 4; e++) o[nt][e] = 0.0f;
    float mrow0 = -1e30f, mrow1 = -1e30f;
    float lrow0 = 0.0f,   lrow1 = 0.0f;

    for (int kt = 0; kt <= qb; kt++) {
        if (kt < qb) CP_WAIT1(); else CP_WAIT0();
        __syncthreads();

        uint32_t kb = sbase + 16384 + (kt % 3) * 32768;
        uint32_t vb = kb + 16384;
        int k0 = kt * 64;

        // ---- S = Q K^T : m16 x n64 x k128 ----
        float s[8][4];
#pragma unroll
        for (int nt = 0; nt < 8; nt++)
#pragma unroll
            for (int e = 0; e < 4; e++) s[nt][e] = 0.0f;
#pragma unroll
        for (int ks = 0; ks < 8; ks++) {
            uint4 aq;
            {
                int row = w * 16 + ((sel & 1) << 3) + lrow;
                int ch  = ks * 2 + (sel >> 1);
                ldm4(aq, sbase + sw256(row, ch));
            }
#pragma unroll
            for (int nt = 0; nt < 4; nt++) {
                int row = nt * 16 + ((sel >> 1) << 3) + lrow;
                int ch  = ks * 2 + (sel & 1);
                uint4 bk;
                ldm4(bk, kb + sw256(row, ch));
                mma_h(s[2 * nt],     aq.x, aq.y, aq.z, aq.w, bk.x, bk.y);
                mma_h(s[2 * nt + 1], aq.x, aq.y, aq.z, aq.w, bk.z, bk.w);
            }
        }

        // ---- causal mask (scale folded into Q) ----
        if (kt == qb) {
            int row0 = q0 + w * 16 + g;
#pragma unroll
            for (int nt = 0; nt < 8; nt++)
#pragma unroll
                for (int e2 = 0; e2 < 4; e2++) {
                    int col = k0 + nt * 8 + tg * 2 + (e2 & 1);
                    int rr = row0 + (e2 >> 1) * 8;
                    if (col > rr) s[nt][e2] = -1e30f;
                }
        }

        // ---- warp-local softmax state ----
        float mx0 = -1e30f, mx1 = -1e30f;
#pragma unroll
        for (int nt = 0; nt < 8; nt++) {
            mx0 = fmaxf(mx0, fmaxf(s[nt][0], s[nt][1]));
            mx1 = fmaxf(mx1, fmaxf(s[nt][2], s[nt][3]));
        }
        mx0 = fmaxf(mx0, __shfl_xor_sync(0xffffffffu, mx0, 1));
        mx0 = fmaxf(mx0, __shfl_xor_sync(0xffffffffu, mx0, 2));
        mx1 = fmaxf(mx1, __shfl_xor_sync(0xffffffffu, mx1, 1));
        mx1 = fmaxf(mx1, __shfl_xor_sync(0xffffffffu, mx1, 2));

        float mn0 = fmaxf(mrow0, mx0);
        float mn1 = fmaxf(mrow1, mx1);
        float al0 = __expf(mrow0 - mn0);
        float al1 = __expf(mrow1 - mn1);
        mrow0 = mn0; mrow1 = mn1;

        float rs0 = 0.0f, rs1 = 0.0f;
#pragma unroll
        for (int nt = 0; nt < 8; nt++) {
            float p0 = __expf(s[nt][0] - mn0);
            float p1 = __expf(s[nt][1] - mn0);
            float p2 = __expf(s[nt][2] - mn1);
            float p3 = __expf(s[nt][3] - mn1);
            rs0 += p0 + p1; rs1 += p2 + p3;
            s[nt][0] = p0; s[nt][1] = p1; s[nt][2] = p2; s[nt][3] = p3;
        }
        rs0 += __shfl_xor_sync(0xffffffffu, rs0, 1);
        rs0 += __shfl_xor_sync(0xffffffffu, rs0, 2);
        rs1 += __shfl_xor_sync(0xffffffffu, rs1, 1);
        rs1 += __shfl_xor_sync(0xffffffffu, rs1, 2);
        lrow0 = lrow0 * al0 + rs0;
        lrow1 = lrow1 * al1 + rs1;

#pragma unroll
        for (int nt = 0; nt < 16; nt++) {
            o[nt][0] *= al0; o[nt][1] *= al0;
            o[nt][2] *= al1; o[nt][3] *= al1;
        }

        // ---- O += P @ V : P fragments packed from registers (no smem) ----
#pragma unroll
        for (int ks2 = 0; ks2 < 4; ks2++) {
            unsigned a0 = h2pack(s[2 * ks2][0],     s[2 * ks2][1]);
            unsigned a1 = h2pack(s[2 * ks2][2],     s[2 * ks2][3]);
            unsigned a2 = h2pack(s[2 * ks2 + 1][0], s[2 * ks2 + 1][1]);
            unsigned a3 = h2pack(s[2 * ks2 + 1][2], s[2 * ks2 + 1][3]);
#pragma unroll
            for (int nt = 0; nt < 8; nt++) {
                int row = ks2 * 16 + ((sel & 1) << 3) + lrow;
                int ch  = nt * 2 + (sel >> 1);
                uint4 bv;
                ldm4t(bv, vb + sw256(row, ch));
                mma_h(o[2 * nt],     a0, a1, a2, a3, bv.x, bv.y);
                mma_h(o[2 * nt + 1], a0, a1, a2, a3, bv.z, bv.w);
            }
        }

        if (kt + 2 <= qb) ISSUE_KV(kt + 2);
    }
#undef ISSUE_KV

    // ---- epilogue -> g_yh fp16 [b,t,c] ----
    int b = bh >> 4;
    int hh = bh & 15;
#pragma unroll
    for (int h = 0; h < 2; h++) {
        float invl = 1.0f / (h ? lrow1 : lrow0);
        int t = q0 + w * 16 + g + h * 8;
        __half* op = g_yh + ((size_t)(b * Tv + t)) * Cv + hh * HDv;
#pragma unroll
        for (int nt = 0; nt < 16; nt++) {
            int d = nt * 8 + tg * 2;
            *(unsigned*)&op[d] = h2pack(o[nt][2 * h] * invl, o[nt][2 * h + 1] * invl);
        }
    }
}

// ---------------- launch ----------------
extern "C" void kernel_launch(void* const* d_in, const int* in_sizes, int n_in,
                              void* d_out, int out_size)
{
    const float* x  = (const float*)d_in[0];
    const float* wq = (const float*)d_in[2];
    const float* wk = (const float*)d_in[3];
    const float* wv = (const float*)d_in[4];
    const float* wo = (const float*)d_in[5];
    float* out = (float*)d_out;

    const size_t NX = (size_t)Bv * Tv * Cv;
    const size_t NW = (size_t)Cv * Cv;

    cvt_kernel<<<NX / 1024, 256>>>(x, 0, 0);
    cvt_kernel<<<NW / 1024, 256>>>(wq, 1, 0 * NW);
    cvt_kernel<<<NW / 1024, 256>>>(wk, 1, 1 * NW);
    cvt_kernel<<<NW / 1024, 256>>>(wv, 1, 2 * NW);
    cvt_kernel<<<NW / 1024, 256>>>(wo, 1, 3 * NW);

    static __half* whp = nullptr;
    static __half* xhp = nullptr;
    static __half* yhp = nullptr;
    if (!whp) {
        cudaGetSymbolAddress((void**)&whp, g_wh);
        cudaGetSymbolAddress((void**)&xhp, g_xh);
        cudaGetSymbolAddress((void**)&yhp, g_yh);
        cudaFuncSetAttribute(h16gemm, cudaFuncAttributeMaxDynamicSharedMemorySize,
                             GEMM_SMEM_BYTES);
        cudaFuncSetAttribute(attn_kernel, cudaFuncAttributeMaxDynamicSharedMemorySize,
                             ATT_SMEM_BYTES);
    }

    dim3 gg(Cv / 128, (Bv * Tv) / 128);  // (16, 64)

    h16gemm<<<gg, 256, GEMM_SMEM_BYTES>>>(xhp, whp + 0 * NW, nullptr, 0);
    h16gemm<<<gg, 256, GEMM_SMEM_BYTES>>>(xhp, whp + 1 * NW, nullptr, 1);
    h16gemm<<<gg, 256, GEMM_SMEM_BYTES>>>(xhp, whp + 2 * NW, nullptr, 2);

    rope_kernel<<<(BHv * Tv * 64) / 256, 256>>>();

    attn_kernel<<<dim3(Tv / 64, BHv), 128, ATT_SMEM_BYTES>>>();

    h16gemm<<<gg, 256, GEMM_SMEM_BYTES>>>(yhp, whp + 3 * NW, out, 3);
}